// round 16
// baseline (speedup 1.0000x reference)
#include <cuda_runtime.h>
#include <cuda_fp16.h>
#include <cstdint>

#define B_      8
#define Hdim    128
#define Wdim    128
#define C_      192
#define L_      (Hdim*Wdim)
#define NHEADS  6
#define HD      32
#define NTOK    128
#define NWIN    128
#define POSDIM  12
#define NBIAS   465
#define SCALE   0.17677669529663687f
#define LOG2E   1.4426950408889634f

// Scratch (device globals)
__device__ __half g_qph[B_*NHEADS*NTOK*HD];     // pooled queries, *SCALE*LOG2E
__device__ float  g_pos[NBIAS*NHEADS];          // pos MLP, *LOG2E
// fragment-permuted combined bias: uint4 idx = (((win*6+h)*8 + slot)*8 + m)*32 + lane
__device__ __half g_biasf[(size_t)NWIN*NHEADS*NTOK*NTOK];

__device__ __forceinline__ float ex2f(float x) {
    asm("ex2.approx.ftz.f32 %0, %1;" : "=f"(x) : "f"(x));
    return x;
}
__device__ __forceinline__ uint32_t smem_u32(const void* p) {
    uint32_t a;
    asm("{ .reg .u64 t; cvta.to.shared.u64 t, %1; cvt.u32.u64 %0, t; }" : "=r"(a) : "l"(p));
    return a;
}
__device__ __forceinline__ void ldm_x4(uint32_t& r0, uint32_t& r1, uint32_t& r2, uint32_t& r3, uint32_t addr) {
    asm volatile("ldmatrix.sync.aligned.m8n8.x4.shared.b16 {%0,%1,%2,%3}, [%4];"
                 : "=r"(r0), "=r"(r1), "=r"(r2), "=r"(r3) : "r"(addr));
}
__device__ __forceinline__ void ldm_x4_t(uint32_t& r0, uint32_t& r1, uint32_t& r2, uint32_t& r3, uint32_t addr) {
    asm volatile("ldmatrix.sync.aligned.m8n8.x4.trans.shared.b16 {%0,%1,%2,%3}, [%4];"
                 : "=r"(r0), "=r"(r1), "=r"(r2), "=r"(r3) : "r"(addr));
}
__device__ __forceinline__ void mma_f16(float* c, const uint32_t* a, uint32_t b0, uint32_t b1) {
    asm volatile(
        "mma.sync.aligned.m16n8k16.row.col.f32.f16.f16.f32 "
        "{%0,%1,%2,%3}, {%4,%5,%6,%7}, {%8,%9}, {%0,%1,%2,%3};"
        : "+f"(c[0]), "+f"(c[1]), "+f"(c[2]), "+f"(c[3])
        : "r"(a[0]), "r"(a[1]), "r"(a[2]), "r"(a[3]), "r"(b0), "r"(b1));
}
__device__ __forceinline__ uint32_t h2u(__half2 h) {
    return *reinterpret_cast<uint32_t*>(&h);
}
__device__ __forceinline__ uint32_t packh2(float a, float b) {
    return h2u(__floats2half2_rn(a, b));
}

// 64B-row swizzle (Q,K,V tiles: 128 rows x 32 half): chunk c in [0,4)
__device__ __forceinline__ uint32_t swz64(int row, int c) {
    return row*64 + ((c ^ ((row >> 1) & 3)) << 4);
}

// smem byte offsets (attn kernel)
#define SM_Q    0
#define SM_K    8192
#define SM_V    16384
#define SM_O    24576           // 128 x 36 fp32 (float4-aligned pitch)
#define OPITCH  36
#define SM_TOT  (24576 + 128*36*4)

// ---------------------------------------------------------------------------
// Launch 1 (384 threads):
//  blocks [0,4): DynamicPosBias MLP -> g_pos (128 threads active);
//  blocks [4,1028): pooled query — float4 loads, 8 pixel-groups, smem combine.
// ---------------------------------------------------------------------------
__global__ void __launch_bounds__(384)
poolpos_kernel(
    const float* __restrict__ q,
    const float* __restrict__ rpe,
    const float* __restrict__ w0, const float* __restrict__ b0,
    const float* __restrict__ g1, const float* __restrict__ be1,
    const float* __restrict__ w1, const float* __restrict__ lb1,
    const float* __restrict__ g2, const float* __restrict__ be2,
    const float* __restrict__ w2, const float* __restrict__ lb2,
    const float* __restrict__ g3, const float* __restrict__ be3,
    const float* __restrict__ w3, const float* __restrict__ lb3)
{
    __shared__ float4 smp[8][48];
    int bx = blockIdx.x;
    int tt = threadIdx.x;
    if (bx < 4) {
        if (tt >= 128) return;
        int t = bx*128 + tt;
        if (t >= NBIAS) return;
        float x[POSDIM], y[POSDIM];
        float a = rpe[2*t], b = rpe[2*t+1];
        #pragma unroll
        for (int o = 0; o < POSDIM; o++)
            x[o] = a * w0[o] + b * w0[POSDIM + o] + b0[o];

        #pragma unroll
        for (int stage = 0; stage < 3; stage++) {
            const float* g  = stage == 0 ? g1  : (stage == 1 ? g2  : g3);
            const float* be = stage == 0 ? be1 : (stage == 1 ? be2 : be3);
            float m = 0.f;
            #pragma unroll
            for (int i = 0; i < POSDIM; i++) m += x[i];
            m *= (1.f/POSDIM);
            float v = 0.f;
            #pragma unroll
            for (int i = 0; i < POSDIM; i++) { float d = x[i]-m; v += d*d; }
            v *= (1.f/POSDIM);
            float inv = rsqrtf(v + 1e-5f);
            #pragma unroll
            for (int i = 0; i < POSDIM; i++)
                y[i] = fmaxf((x[i]-m)*inv*g[i] + be[i], 0.f);
            if (stage < 2) {
                const float* w  = stage == 0 ? w1  : w2;
                const float* lb = stage == 0 ? lb1 : lb2;
                #pragma unroll
                for (int o = 0; o < POSDIM; o++) {
                    float s = lb[o];
                    #pragma unroll
                    for (int i = 0; i < POSDIM; i++) s += y[i] * w[i*POSDIM + o];
                    x[o] = s;
                }
            } else {
                #pragma unroll
                for (int o = 0; o < NHEADS; o++) {
                    float s = lb3[o];
                    #pragma unroll
                    for (int i = 0; i < POSDIM; i++) s += y[i] * w3[i*NHEADS + o];
                    g_pos[t*NHEADS + o] = s * LOG2E;
                }
            }
        }
    } else {
        // ---- pool: one block per (token n, batch b); thread = (pg, c4) ----
        int bi = bx - 4;
        int b = bi >> 7;
        int n = bi & 127;
        int c4 = tt % 48;            // float4 index in channel dim (4 channels)
        int pg = tt / 48;            // pixel group 0..7
        int i = n >> 4;
        int j = n & 15;
        bool is_avg = (c4 < 24);
        const float4* base = (const float4*)(q + ((size_t)b * L_) * C_) + c4;
        float4 acc = is_avg ? make_float4(0.f, 0.f, 0.f, 0.f)
                            : make_float4(-3.0e38f, -3.0e38f, -3.0e38f, -3.0e38f);
        #pragma unroll 4
        for (int pp = 0; pp < 16; pp++) {
            int p = pg + pp*8;       // pixel 0..127 within window
            int y = i*16 + (p >> 3);
            int x = j*8 + (p & 7);
            float4 v = base[(size_t)(y*Wdim + x) * 48];
            if (is_avg) {
                acc.x += v.x; acc.y += v.y; acc.z += v.z; acc.w += v.w;
            } else {
                acc.x = fmaxf(acc.x, v.x); acc.y = fmaxf(acc.y, v.y);
                acc.z = fmaxf(acc.z, v.z); acc.w = fmaxf(acc.w, v.w);
            }
        }
        smp[pg][c4] = acc;
        __syncthreads();
        if (tt < 48) {
            float4 r = smp[0][tt];
            #pragma unroll
            for (int gg = 1; gg < 8; gg++) {
                float4 v = smp[gg][tt];
                if (is_avg) {
                    r.x += v.x; r.y += v.y; r.z += v.z; r.w += v.w;
                } else {
                    r.x = fmaxf(r.x, v.x); r.y = fmaxf(r.y, v.y);
                    r.z = fmaxf(r.z, v.z); r.w = fmaxf(r.w, v.w);
                }
            }
            float k = SCALE * LOG2E;
            if (is_avg) k *= (1.f/128.f);
            int c0 = tt*4;
            int h = c0 >> 5, d = c0 & 31;
            uint2 o = make_uint2(packh2(r.x*k, r.y*k), packh2(r.z*k, r.w*k));
            *(uint2*)(g_qph + (((b*NHEADS) + h)*NTOK + n)*HD + d) = o;
        }
    }
}

// ---------------------------------------------------------------------------
// Launch 2: combined permuted bias. One block per win (128 blocks, 256 thr);
// mask/rel loaded once per element, reused across all 6 heads.
// ---------------------------------------------------------------------------
__global__ void bias_kernel(const float* __restrict__ mask,
                            const int* __restrict__ rel_idx)
{
    __shared__ float pos_s[NBIAS*NHEADS];   // [r][h], *LOG2E already
    int win = blockIdx.x;
    int t   = threadIdx.x;
    for (int i = t; i < NBIAS*NHEADS; i += 256)
        pos_s[i] = g_pos[i];
    __syncthreads();

    int slot = t >> 5;        // 8 slots (warps)
    int lane = t & 31;
    int g   = lane >> 2;
    int tig = lane & 3;
    const float* maskp = mask + ((size_t)win << 14);
    int i0 = slot*16 + g;
    #pragma unroll
    for (int m = 0; m < 8; m++) {
        float2 mm[4];
        int2   rr[4];
        #pragma unroll
        for (int sub = 0; sub < 2; sub++) {
            int j0 = (2*m + sub)*8 + tig*2;
            #pragma unroll
            for (int r = 0; r < 2; r++) {
                int i = i0 + r*8;
                rr[sub*2 + r] = *(const int2*)(rel_idx + i*NTOK + j0);
                mm[sub*2 + r] = *(const float2*)(maskp + i*NTOK + j0);
            }
        }
        #pragma unroll
        for (int e = 0; e < 4; e++) {
            mm[e].x *= LOG2E;
            mm[e].y *= LOG2E;
        }
        #pragma unroll
        for (int h = 0; h < NHEADS; h++) {
            uint32_t wv[4];
            #pragma unroll
            for (int e = 0; e < 4; e++)
                wv[e] = packh2(pos_s[rr[e].x*NHEADS + h] + mm[e].x,
                               pos_s[rr[e].y*NHEADS + h] + mm[e].y);
            uint4* outp = (uint4*)g_biasf
                + ((((size_t)win*NHEADS + h)*8 + slot)*8 + m)*32 + lane;
            *outp = make_uint4(wv[0], wv[1], wv[2], wv[3]);
        }
    }
}

// ---------------------------------------------------------------------------
// Launch 3: fused attention (R12-verified body).
// grid=(6,1024), block=256 (8 warps), ~43KB smem, 2 blocks/SM.
// ---------------------------------------------------------------------------
__global__ void __launch_bounds__(256, 2)
attn_kernel(const float* __restrict__ kg, const float* __restrict__ vg,
            float* __restrict__ outg)
{
    extern __shared__ char smem[];
    const uint32_t sbase = smem_u32(smem);
    float* out_s = (float*)(smem + SM_O);

    const int t    = threadIdx.x;
    const int warp = t >> 5;
    const int lane = t & 31;
    const int g    = lane >> 2;
    const int tig  = lane & 3;
    const int h    = blockIdx.x;
    const int w    = blockIdx.y;
    const int b    = w >> 7;
    const int win  = w & 127;
    const int hb   = win >> 3;
    const int wb   = win & 7;
    const int qb   = w & 7;

    // ---- load Q (half) + K/V (fp32 -> half) into swizzled smem ----
    {
        const __half* qsrc = g_qph + (((size_t)qb*NHEADS + h)*NTOK)*HD;
        #pragma unroll
        for (int rep = 0; rep < 4; rep++) {
            int idx = t + rep*256;              // 8B chunk id
            int row = idx >> 3, q4 = idx & 7;
            uint32_t off = swz64(row, q4 >> 1) + ((q4 & 1) << 3);
            *(uint2*)(smem + SM_Q + off) = *(const uint2*)(qsrc + idx*4);
        }
        #pragma unroll
        for (int rep = 0; rep < 4; rep++) {
            int idx = t + rep*256;
            int row = idx >> 3, q4 = idx & 7;
            int y = hb*8 + (row >> 4);
            int x = wb*16 + (row & 15);
            size_t goff = ((size_t)(b*L_ + y*Wdim + x))*C_ + h*HD + q4*4;
            uint32_t off = swz64(row, q4 >> 1) + ((q4 & 1) << 3);
            float4 kv = *(const float4*)(kg + goff);
            *(uint2*)(smem + SM_K + off) =
                make_uint2(packh2(kv.x, kv.y), packh2(kv.z, kv.w));
            float4 vv = *(const float4*)(vg + goff);
            *(uint2*)(smem + SM_V + off) =
                make_uint2(packh2(vv.x, vv.y), packh2(vv.z, vv.w));
        }
    }
    __syncthreads();

    const int i0 = warp * 16;      // this warp owns rows [i0, i0+16)

    // ---- prefetch permuted bias: 8 x LDG.128 per thread, coalesced ----
    uint4 Bb[8];
    {
        const uint4* bf = (const uint4*)g_biasf
            + ((((size_t)win*NHEADS + h)*8 + warp)*8)*32 + lane;
        #pragma unroll
        for (int m = 0; m < 8; m++)
            Bb[m] = bf[m*32];
    }

    // ---- QK^T: warp tile 16 rows x 128 cols ----
    float acc[16][4];
    {
        uint32_t A[2][4];
        #pragma unroll
        for (int ks = 0; ks < 2; ks++) {
            int row = i0 + (lane & 15);
            int c   = 2*ks + (lane >> 4);
            ldm_x4(A[ks][0], A[ks][1], A[ks][2], A[ks][3], sbase + SM_Q + swz64(row, c));
        }
        #pragma unroll
        for (int nt = 0; nt < 16; nt++)
            #pragma unroll
            for (int k = 0; k < 4; k++) acc[nt][k] = 0.f;

        #pragma unroll
        for (int ntp = 0; ntp < 8; ntp++) {
            #pragma unroll
            for (int ks = 0; ks < 2; ks++) {
                uint32_t Bv[4];
                int rowj = ntp*16 + (lane & 7) + ((lane >> 4) << 3);
                int c    = 2*ks + ((lane >> 3) & 1);
                ldm_x4(Bv[0], Bv[1], Bv[2], Bv[3], sbase + SM_K + swz64(rowj, c));
                mma_f16(acc[2*ntp],     A[ks], Bv[0], Bv[1]);
                mma_f16(acc[2*ntp + 1], A[ks], Bv[2], Bv[3]);
            }
        }
    }

    // ---- add bias (fragment-layout regs), register softmax, pack P ----
    uint32_t ph[8][4];
    float inv0, inv1;
    {
        float m0 = -3.0e38f, m1 = -3.0e38f;
        #pragma unroll
        for (int nt = 0; nt < 16; nt++) {
            int m = nt >> 1;
            uint32_t u0 = (nt & 1) ? Bb[m].z : Bb[m].x;
            uint32_t u1 = (nt & 1) ? Bb[m].w : Bb[m].y;
            float2 bv0 = __half22float2(*reinterpret_cast<__half2*>(&u0));
            float2 bv1 = __half22float2(*reinterpret_cast<__half2*>(&u1));
            acc[nt][0] += bv0.x; acc[nt][1] += bv0.y;
            acc[nt][2] += bv1.x; acc[nt][3] += bv1.y;
            m0 = fmaxf(m0, fmaxf(acc[nt][0], acc[nt][1]));
            m1 = fmaxf(m1, fmaxf(acc[nt][2], acc[nt][3]));
        }
        m0 = fmaxf(m0, __shfl_xor_sync(0xffffffffu, m0, 1));
        m0 = fmaxf(m0, __shfl_xor_sync(0xffffffffu, m0, 2));
        m1 = fmaxf(m1, __shfl_xor_sync(0xffffffffu, m1, 1));
        m1 = fmaxf(m1, __shfl_xor_sync(0xffffffffu, m1, 2));

        float s0 = 0.f, s1 = 0.f;
        #pragma unroll
        for (int nt = 0; nt < 16; nt++) {
            float e0 = ex2f(acc[nt][0] - m0);
            float e1 = ex2f(acc[nt][1] - m0);
            float e2 = ex2f(acc[nt][2] - m1);
            float e3 = ex2f(acc[nt][3] - m1);
            s0 += e0 + e1;
            s1 += e2 + e3;
            if ((nt & 1) == 0) {
                ph[nt >> 1][0] = packh2(e0, e1);
                ph[nt >> 1][1] = packh2(e2, e3);
            } else {
                ph[nt >> 1][2] = packh2(e0, e1);
                ph[nt >> 1][3] = packh2(e2, e3);
            }
        }
        s0 += __shfl_xor_sync(0xffffffffu, s0, 1);
        s0 += __shfl_xor_sync(0xffffffffu, s0, 2);
        s1 += __shfl_xor_sync(0xffffffffu, s1, 1);
        s1 += __shfl_xor_sync(0xffffffffu, s1, 2);
        inv0 = __fdividef(1.f, s0);
        inv1 = __fdividef(1.f, s1);
    }

    // ---- P @ V: rows [i0, i0+16), cols 0..31 -> smem staging ----
    {
        float o[4][4];
        #pragma unroll
        for (int nt = 0; nt < 4; nt++)
            #pragma unroll
            for (int k = 0; k < 4; k++) o[nt][k] = 0.f;

        #pragma unroll
        for (int ks = 0; ks < 8; ks++) {
            #pragma unroll
            for (int ntp = 0; ntp < 2; ntp++) {
                uint32_t Bv[4];
                int rowk = ks*16 + (lane & 7) + (((lane >> 3) & 1) << 3);
                int c    = 2*ntp + (lane >> 4);
                ldm_x4_t(Bv[0], Bv[1], Bv[2], Bv[3], sbase + SM_V + swz64(rowk, c));
                mma_f16(o[2*ntp],     ph[ks], Bv[0], Bv[1]);
                mma_f16(o[2*ntp + 1], ph[ks], Bv[2], Bv[3]);
            }
        }
        #pragma unroll
        for (int nt = 0; nt < 4; nt++) {
            int d = nt*8 + 2*tig;
            float* p0 = out_s + (i0 + g)*OPITCH + d;
            p0[0] = o[nt][0]*inv0; p0[1] = o[nt][1]*inv0;
            float* p1 = out_s + (i0 + g + 8)*OPITCH + d;
            p1[0] = o[nt][2]*inv1; p1[1] = o[nt][3]*inv1;
        }
    }
    __syncthreads();

    // ---- cooperative coalesced output store (LDS.128-aligned staging) ----
    {
        #pragma unroll
        for (int rep = 0; rep < 4; rep++) {
            int idx = t + rep*256;        // float4 id, 1024 total
            int row = idx >> 3, q4 = idx & 7;
            float4 v4 = *(const float4*)(out_s + row*OPITCH + q4*4);
            int y = hb*8 + (row >> 4);
            int x = wb*16 + (row & 15);
            float* op = outg + ((size_t)((b*Hdim + y)*Wdim + x))*C_ + h*HD + q4*4;
            *(float4*)op = v4;
        }
    }
}

// ---------------------------------------------------------------------------
extern "C" void kernel_launch(void* const* d_in, const int* in_sizes, int n_in,
                              void* d_out, int out_size)
{
    const float* qkv  = (const float*)d_in[0];
    const float* mask = (const float*)d_in[1];
    const float* w0   = (const float*)d_in[2];
    const float* b0   = (const float*)d_in[3];
    const float* g1   = (const float*)d_in[4];
    const float* be1  = (const float*)d_in[5];
    const float* w1   = (const float*)d_in[6];
    const float* lb1  = (const float*)d_in[7];
    const float* g2   = (const float*)d_in[8];
    const float* be2  = (const float*)d_in[9];
    const float* w2   = (const float*)d_in[10];
    const float* lb2  = (const float*)d_in[11];
    const float* g3   = (const float*)d_in[12];
    const float* be3  = (const float*)d_in[13];
    const float* w3   = (const float*)d_in[14];
    const float* lb3  = (const float*)d_in[15];
    const float* rpe  = (const float*)d_in[16];
    const int*   rel  = (const int*)d_in[17];

    const float* q_g = qkv;
    const float* k_g = qkv + (size_t)B_ * L_ * C_;
    const float* v_g = qkv + 2 * (size_t)B_ * L_ * C_;
    float* out = (float*)d_out;

    poolpos_kernel<<<4 + 1024, 384>>>(q_g, rpe,
                                      w0, b0, g1, be1, w1, lb1,
                                      g2, be2, w2, lb2, g3, be3, w3, lb3);
    bias_kernel<<<NWIN, 256>>>(mask, rel);

    cudaFuncSetAttribute(attn_kernel, cudaFuncAttributeMaxDynamicSharedMemorySize, SM_TOT);
    attn_kernel<<<dim3(NHEADS, B_*NWIN), 256, SM_TOT>>>(k_g, v_g, out);
}

// round 17
// speedup vs baseline: 1.0372x; 1.0372x over previous
#include <cuda_runtime.h>
#include <cuda_fp16.h>
#include <cstdint>

#define B_      8
#define Hdim    128
#define Wdim    128
#define C_      192
#define L_      (Hdim*Wdim)
#define NHEADS  6
#define HD      32
#define NTOK    128
#define NWIN    128
#define POSDIM  12
#define NBIAS   465
#define SCALE   0.17677669529663687f
#define LOG2E   1.4426950408889634f

// Scratch (device globals)
__device__ __half g_qph[B_*NHEADS*NTOK*HD];     // pooled queries, *SCALE*LOG2E
__device__ float  g_pos[NBIAS*NHEADS];          // pos MLP, *LOG2E
// fragment-permuted combined bias: uint4 idx = (((win*6+h)*8 + slot)*8 + m)*32 + lane
__device__ __half g_biasf[(size_t)NWIN*NHEADS*NTOK*NTOK];

__device__ __forceinline__ float ex2f(float x) {
    asm("ex2.approx.ftz.f32 %0, %1;" : "=f"(x) : "f"(x));
    return x;
}
__device__ __forceinline__ uint32_t smem_u32(const void* p) {
    uint32_t a;
    asm("{ .reg .u64 t; cvta.to.shared.u64 t, %1; cvt.u32.u64 %0, t; }" : "=r"(a) : "l"(p));
    return a;
}
__device__ __forceinline__ void ldm_x4(uint32_t& r0, uint32_t& r1, uint32_t& r2, uint32_t& r3, uint32_t addr) {
    asm volatile("ldmatrix.sync.aligned.m8n8.x4.shared.b16 {%0,%1,%2,%3}, [%4];"
                 : "=r"(r0), "=r"(r1), "=r"(r2), "=r"(r3) : "r"(addr));
}
__device__ __forceinline__ void ldm_x4_t(uint32_t& r0, uint32_t& r1, uint32_t& r2, uint32_t& r3, uint32_t addr) {
    asm volatile("ldmatrix.sync.aligned.m8n8.x4.trans.shared.b16 {%0,%1,%2,%3}, [%4];"
                 : "=r"(r0), "=r"(r1), "=r"(r2), "=r"(r3) : "r"(addr));
}
__device__ __forceinline__ void mma_f16(float* c, const uint32_t* a, uint32_t b0, uint32_t b1) {
    asm volatile(
        "mma.sync.aligned.m16n8k16.row.col.f32.f16.f16.f32 "
        "{%0,%1,%2,%3}, {%4,%5,%6,%7}, {%8,%9}, {%0,%1,%2,%3};"
        : "+f"(c[0]), "+f"(c[1]), "+f"(c[2]), "+f"(c[3])
        : "r"(a[0]), "r"(a[1]), "r"(a[2]), "r"(a[3]), "r"(b0), "r"(b1));
}
__device__ __forceinline__ uint32_t h2u(__half2 h) {
    return *reinterpret_cast<uint32_t*>(&h);
}
__device__ __forceinline__ uint32_t packh2(float a, float b) {
    return h2u(__floats2half2_rn(a, b));
}

// 64B-row swizzle (Q,K,V tiles: 128 rows x 32 half): chunk c in [0,4)
__device__ __forceinline__ uint32_t swz64(int row, int c) {
    return row*64 + ((c ^ ((row >> 1) & 3)) << 4);
}

// smem byte offsets (attn kernel)
#define SM_Q    0
#define SM_K    8192
#define SM_V    16384
#define SM_O    24576           // 128 x 36 fp32 (float4-aligned pitch)
#define OPITCH  36
#define SM_TOT  (24576 + 128*36*4)

// ---------------------------------------------------------------------------
// Launch 1 (256 threads) — R9-verified (21.2 us):
//  blocks [0,4): DynamicPosBias MLP -> g_pos (128 threads active);
//  blocks [4,1028): pooled query (192 threads active).
// ---------------------------------------------------------------------------
__global__ void poolpos_kernel(
    const float* __restrict__ q,
    const float* __restrict__ rpe,
    const float* __restrict__ w0, const float* __restrict__ b0,
    const float* __restrict__ g1, const float* __restrict__ be1,
    const float* __restrict__ w1, const float* __restrict__ lb1,
    const float* __restrict__ g2, const float* __restrict__ be2,
    const float* __restrict__ w2, const float* __restrict__ lb2,
    const float* __restrict__ g3, const float* __restrict__ be3,
    const float* __restrict__ w3, const float* __restrict__ lb3)
{
    int bx = blockIdx.x;
    int tt = threadIdx.x;
    if (bx < 4) {
        if (tt >= 128) return;
        int t = bx*128 + tt;
        if (t >= NBIAS) return;
        float x[POSDIM], y[POSDIM];
        float a = rpe[2*t], b = rpe[2*t+1];
        #pragma unroll
        for (int o = 0; o < POSDIM; o++)
            x[o] = a * w0[o] + b * w0[POSDIM + o] + b0[o];

        #pragma unroll
        for (int stage = 0; stage < 3; stage++) {
            const float* g  = stage == 0 ? g1  : (stage == 1 ? g2  : g3);
            const float* be = stage == 0 ? be1 : (stage == 1 ? be2 : be3);
            float m = 0.f;
            #pragma unroll
            for (int i = 0; i < POSDIM; i++) m += x[i];
            m *= (1.f/POSDIM);
            float v = 0.f;
            #pragma unroll
            for (int i = 0; i < POSDIM; i++) { float d = x[i]-m; v += d*d; }
            v *= (1.f/POSDIM);
            float inv = rsqrtf(v + 1e-5f);
            #pragma unroll
            for (int i = 0; i < POSDIM; i++)
                y[i] = fmaxf((x[i]-m)*inv*g[i] + be[i], 0.f);
            if (stage < 2) {
                const float* w  = stage == 0 ? w1  : w2;
                const float* lb = stage == 0 ? lb1 : lb2;
                #pragma unroll
                for (int o = 0; o < POSDIM; o++) {
                    float s = lb[o];
                    #pragma unroll
                    for (int i = 0; i < POSDIM; i++) s += y[i] * w[i*POSDIM + o];
                    x[o] = s;
                }
            } else {
                #pragma unroll
                for (int o = 0; o < NHEADS; o++) {
                    float s = lb3[o];
                    #pragma unroll
                    for (int i = 0; i < POSDIM; i++) s += y[i] * w3[i*NHEADS + o];
                    g_pos[t*NHEADS + o] = s * LOG2E;
                }
            }
        }
    } else {
        // ---- pool: one block per (token n, batch b) ----
        int bi = bx - 4;
        int b = bi >> 7;
        int n = bi & 127;
        int c = tt;
        if (c >= C_) return;
        int i = n >> 4;
        int j = n & 15;
        const float* base = q + ((size_t)b * L_) * C_ + c;
        bool is_avg = (c < 96);
        float acc = is_avg ? 0.f : -3.0e38f;
        #pragma unroll 4
        for (int yy = 0; yy < 16; yy++) {
            int y = i*16 + yy;
            const float* row = base + (size_t)(y*Wdim + j*8) * C_;
            #pragma unroll
            for (int xx = 0; xx < 8; xx++) {
                float v = row[(size_t)xx * C_];
                if (is_avg) acc += v; else acc = fmaxf(acc, v);
            }
        }
        if (is_avg) acc *= (1.f/128.f);
        int h = c >> 5, d = c & 31;
        g_qph[(((b*NHEADS) + h)*NTOK + n)*HD + d] = __float2half_rn(acc * (SCALE * LOG2E));
    }
}

// ---------------------------------------------------------------------------
// Launch 2: combined permuted bias — R14-verified (~6 us).
// One block per win (128 blocks, 256 thr); mask/rel loaded once per element,
// reused across all 6 heads; pos staged in smem.
// ---------------------------------------------------------------------------
__global__ void bias_kernel(const float* __restrict__ mask,
                            const int* __restrict__ rel_idx)
{
    __shared__ float pos_s[NBIAS*NHEADS];   // [r][h], *LOG2E already
    int win = blockIdx.x;
    int t   = threadIdx.x;
    for (int i = t; i < NBIAS*NHEADS; i += 256)
        pos_s[i] = g_pos[i];
    __syncthreads();

    int slot = t >> 5;        // 8 slots (warps)
    int lane = t & 31;
    int g   = lane >> 2;
    int tig = lane & 3;
    const float* maskp = mask + ((size_t)win << 14);
    int i0 = slot*16 + g;
    #pragma unroll
    for (int m = 0; m < 8; m++) {
        float2 mm[4];
        int2   rr[4];
        #pragma unroll
        for (int sub = 0; sub < 2; sub++) {
            int j0 = (2*m + sub)*8 + tig*2;
            #pragma unroll
            for (int r = 0; r < 2; r++) {
                int i = i0 + r*8;
                rr[sub*2 + r] = *(const int2*)(rel_idx + i*NTOK + j0);
                mm[sub*2 + r] = *(const float2*)(maskp + i*NTOK + j0);
            }
        }
        #pragma unroll
        for (int e = 0; e < 4; e++) {
            mm[e].x *= LOG2E;
            mm[e].y *= LOG2E;
        }
        #pragma unroll
        for (int h = 0; h < NHEADS; h++) {
            uint32_t wv[4];
            #pragma unroll
            for (int e = 0; e < 4; e++)
                wv[e] = packh2(pos_s[rr[e].x*NHEADS + h] + mm[e].x,
                               pos_s[rr[e].y*NHEADS + h] + mm[e].y);
            uint4* outp = (uint4*)g_biasf
                + ((((size_t)win*NHEADS + h)*8 + slot)*8 + m)*32 + lane;
            *outp = make_uint4(wv[0], wv[1], wv[2], wv[3]);
        }
    }
}

// ---------------------------------------------------------------------------
// Launch 3: fused attention — R12/R14-verified body (~85 us).
// grid=(6,1024), block=256 (8 warps), ~43KB smem, 2 blocks/SM.
// ---------------------------------------------------------------------------
__global__ void __launch_bounds__(256, 2)
attn_kernel(const float* __restrict__ kg, const float* __restrict__ vg,
            float* __restrict__ outg)
{
    extern __shared__ char smem[];
    const uint32_t sbase = smem_u32(smem);
    float* out_s = (float*)(smem + SM_O);

    const int t    = threadIdx.x;
    const int warp = t >> 5;
    const int lane = t & 31;
    const int g    = lane >> 2;
    const int tig  = lane & 3;
    const int h    = blockIdx.x;
    const int w    = blockIdx.y;
    const int b    = w >> 7;
    const int win  = w & 127;
    const int hb   = win >> 3;
    const int wb   = win & 7;
    const int qb   = w & 7;

    // ---- load Q (half) + K/V (fp32 -> half) into swizzled smem ----
    {
        const __half* qsrc = g_qph + (((size_t)qb*NHEADS + h)*NTOK)*HD;
        #pragma unroll
        for (int rep = 0; rep < 4; rep++) {
            int idx = t + rep*256;              // 8B chunk id
            int row = idx >> 3, q4 = idx & 7;
            uint32_t off = swz64(row, q4 >> 1) + ((q4 & 1) << 3);
            *(uint2*)(smem + SM_Q + off) = *(const uint2*)(qsrc + idx*4);
        }
        #pragma unroll
        for (int rep = 0; rep < 4; rep++) {
            int idx = t + rep*256;
            int row = idx >> 3, q4 = idx & 7;
            int y = hb*8 + (row >> 4);
            int x = wb*16 + (row & 15);
            size_t goff = ((size_t)(b*L_ + y*Wdim + x))*C_ + h*HD + q4*4;
            uint32_t off = swz64(row, q4 >> 1) + ((q4 & 1) << 3);
            float4 kv = *(const float4*)(kg + goff);
            *(uint2*)(smem + SM_K + off) =
                make_uint2(packh2(kv.x, kv.y), packh2(kv.z, kv.w));
            float4 vv = *(const float4*)(vg + goff);
            *(uint2*)(smem + SM_V + off) =
                make_uint2(packh2(vv.x, vv.y), packh2(vv.z, vv.w));
        }
    }
    __syncthreads();

    const int i0 = warp * 16;      // this warp owns rows [i0, i0+16)

    // ---- prefetch permuted bias: 8 x LDG.128 per thread, coalesced ----
    uint4 Bb[8];
    {
        const uint4* bf = (const uint4*)g_biasf
            + ((((size_t)win*NHEADS + h)*8 + warp)*8)*32 + lane;
        #pragma unroll
        for (int m = 0; m < 8; m++)
            Bb[m] = bf[m*32];
    }

    // ---- QK^T: warp tile 16 rows x 128 cols ----
    float acc[16][4];
    {
        uint32_t A[2][4];
        #pragma unroll
        for (int ks = 0; ks < 2; ks++) {
            int row = i0 + (lane & 15);
            int c   = 2*ks + (lane >> 4);
            ldm_x4(A[ks][0], A[ks][1], A[ks][2], A[ks][3], sbase + SM_Q + swz64(row, c));
        }
        #pragma unroll
        for (int nt = 0; nt < 16; nt++)
            #pragma unroll
            for (int k = 0; k < 4; k++) acc[nt][k] = 0.f;

        #pragma unroll
        for (int ntp = 0; ntp < 8; ntp++) {
            #pragma unroll
            for (int ks = 0; ks < 2; ks++) {
                uint32_t Bv[4];
                int rowj = ntp*16 + (lane & 7) + ((lane >> 4) << 3);
                int c    = 2*ks + ((lane >> 3) & 1);
                ldm_x4(Bv[0], Bv[1], Bv[2], Bv[3], sbase + SM_K + swz64(rowj, c));
                mma_f16(acc[2*ntp],     A[ks], Bv[0], Bv[1]);
                mma_f16(acc[2*ntp + 1], A[ks], Bv[2], Bv[3]);
            }
        }
    }

    // ---- add bias (fragment-layout regs), register softmax, pack P ----
    uint32_t ph[8][4];
    float inv0, inv1;
    {
        float m0 = -3.0e38f, m1 = -3.0e38f;
        #pragma unroll
        for (int nt = 0; nt < 16; nt++) {
            int m = nt >> 1;
            uint32_t u0 = (nt & 1) ? Bb[m].z : Bb[m].x;
            uint32_t u1 = (nt & 1) ? Bb[m].w : Bb[m].y;
            float2 bv0 = __half22float2(*reinterpret_cast<__half2*>(&u0));
            float2 bv1 = __half22float2(*reinterpret_cast<__half2*>(&u1));
            acc[nt][0] += bv0.x; acc[nt][1] += bv0.y;
            acc[nt][2] += bv1.x; acc[nt][3] += bv1.y;
            m0 = fmaxf(m0, fmaxf(acc[nt][0], acc[nt][1]));
            m1 = fmaxf(m1, fmaxf(acc[nt][2], acc[nt][3]));
        }
        m0 = fmaxf(m0, __shfl_xor_sync(0xffffffffu, m0, 1));
        m0 = fmaxf(m0, __shfl_xor_sync(0xffffffffu, m0, 2));
        m1 = fmaxf(m1, __shfl_xor_sync(0xffffffffu, m1, 1));
        m1 = fmaxf(m1, __shfl_xor_sync(0xffffffffu, m1, 2));

        float s0 = 0.f, s1 = 0.f;
        #pragma unroll
        for (int nt = 0; nt < 16; nt++) {
            float e0 = ex2f(acc[nt][0] - m0);
            float e1 = ex2f(acc[nt][1] - m0);
            float e2 = ex2f(acc[nt][2] - m1);
            float e3 = ex2f(acc[nt][3] - m1);
            s0 += e0 + e1;
            s1 += e2 + e3;
            if ((nt & 1) == 0) {
                ph[nt >> 1][0] = packh2(e0, e1);
                ph[nt >> 1][1] = packh2(e2, e3);
            } else {
                ph[nt >> 1][2] = packh2(e0, e1);
                ph[nt >> 1][3] = packh2(e2, e3);
            }
        }
        s0 += __shfl_xor_sync(0xffffffffu, s0, 1);
        s0 += __shfl_xor_sync(0xffffffffu, s0, 2);
        s1 += __shfl_xor_sync(0xffffffffu, s1, 1);
        s1 += __shfl_xor_sync(0xffffffffu, s1, 2);
        inv0 = __fdividef(1.f, s0);
        inv1 = __fdividef(1.f, s1);
    }

    // ---- P @ V: rows [i0, i0+16), cols 0..31 -> smem staging ----
    {
        float o[4][4];
        #pragma unroll
        for (int nt = 0; nt < 4; nt++)
            #pragma unroll
            for (int k = 0; k < 4; k++) o[nt][k] = 0.f;

        #pragma unroll
        for (int ks = 0; ks < 8; ks++) {
            #pragma unroll
            for (int ntp = 0; ntp < 2; ntp++) {
                uint32_t Bv[4];
                int rowk = ks*16 + (lane & 7) + (((lane >> 3) & 1) << 3);
                int c    = 2*ntp + (lane >> 4);
                ldm_x4_t(Bv[0], Bv[1], Bv[2], Bv[3], sbase + SM_V + swz64(rowk, c));
                mma_f16(o[2*ntp],     ph[ks], Bv[0], Bv[1]);
                mma_f16(o[2*ntp + 1], ph[ks], Bv[2], Bv[3]);
            }
        }
        #pragma unroll
        for (int nt = 0; nt < 4; nt++) {
            int d = nt*8 + 2*tig;
            float* p0 = out_s + (i0 + g)*OPITCH + d;
            p0[0] = o[nt][0]*inv0; p0[1] = o[nt][1]*inv0;
            float* p1 = out_s + (i0 + g + 8)*OPITCH + d;
            p1[0] = o[nt][2]*inv1; p1[1] = o[nt][3]*inv1;
        }
    }
    __syncthreads();

    // ---- cooperative coalesced output store (LDS.128-aligned staging) ----
    {
        #pragma unroll
        for (int rep = 0; rep < 4; rep++) {
            int idx = t + rep*256;        // float4 id, 1024 total
            int row = idx >> 3, q4 = idx & 7;
            float4 v4 = *(const float4*)(out_s + row*OPITCH + q4*4);
            int y = hb*8 + (row >> 4);
            int x = wb*16 + (row & 15);
            float* op = outg + ((size_t)((b*Hdim + y)*Wdim + x))*C_ + h*HD + q4*4;
            *(float4*)op = v4;
        }
    }
}

// ---------------------------------------------------------------------------
extern "C" void kernel_launch(void* const* d_in, const int* in_sizes, int n_in,
                              void* d_out, int out_size)
{
    const float* qkv  = (const float*)d_in[0];
    const float* mask = (const float*)d_in[1];
    const float* w0   = (const float*)d_in[2];
    const float* b0   = (const float*)d_in[3];
    const float* g1   = (const float*)d_in[4];
    const float* be1  = (const float*)d_in[5];
    const float* w1   = (const float*)d_in[6];
    const float* lb1  = (const float*)d_in[7];
    const float* g2   = (const float*)d_in[8];
    const float* be2  = (const float*)d_in[9];
    const float* w2   = (const float*)d_in[10];
    const float* lb2  = (const float*)d_in[11];
    const float* g3   = (const float*)d_in[12];
    const float* be3  = (const float*)d_in[13];
    const float* w3   = (const float*)d_in[14];
    const float* lb3  = (const float*)d_in[15];
    const float* rpe  = (const float*)d_in[16];
    const int*   rel  = (const int*)d_in[17];

    const float* q_g = qkv;
    const float* k_g = qkv + (size_t)B_ * L_ * C_;
    const float* v_g = qkv + 2 * (size_t)B_ * L_ * C_;
    float* out = (float*)d_out;

    poolpos_kernel<<<4 + 1024, 256>>>(q_g, rpe,
                                      w0, b0, g1, be1, w1, lb1,
                                      g2, be2, w2, lb2, g3, be3, w3, lb3);
    bias_kernel<<<NWIN, 256>>>(mask, rel);

    cudaFuncSetAttribute(attn_kernel, cudaFuncAttributeMaxDynamicSharedMemorySize, SM_TOT);
    attn_kernel<<<dim3(NHEADS, B_*NWIN), 256, SM_TOT>>>(k_g, v_g, out);
}